// round 1
// baseline (speedup 1.0000x reference)
#include <cuda_runtime.h>
#include <cuda_bf16.h>
#include <math.h>

// ---------------------------------------------------------------------------
// Q6Model: 2-layer ConvLSTM (T=10) + dense head + concat + FC head
// Shapes:
//   x   (8,10,32,32,1)          t,loc (8,1,28,64)
//   L1: Wx1(3,3,1,1024) Wh1(3,3,256,1024) b1(1024)  -> h1 (8,30,30,256)
//   L2: Wx2(3,3,256,512) Wh2(3,3,128,512) b2(512)   -> h2 (8,28,28,128)
//   head: 128->256->64 relu ; concat rows 28=t,29=loc ; 64->64 relu -> 64->1
//   out (8,30,28,1) = 6720 floats
// ---------------------------------------------------------------------------

#define H1N (8*30*30*256)
#define H2N (8*28*28*128)

__device__ float g_h1[H1N];
__device__ float g_c1[H1N];
__device__ float g_h2[H2N];
__device__ float g_c2[H2N];
__device__ float g_gates1[8*30*30*1024];
__device__ float g_gates2[8*28*28*512];
__device__ float g_dh[8*28*28*64];

__global__ void zero_state_kernel() {
    int i = blockIdx.x * blockDim.x + threadIdx.x;
    int stride = gridDim.x * blockDim.x;
    for (int k = i; k < H1N; k += stride) { g_h1[k] = 0.f; g_c1[k] = 0.f; }
    for (int k = i; k < H2N; k += stride) { g_h2[k] = 0.f; g_c2[k] = 0.f; }
}

// ---------------------------------------------------------------------------
// Fused conv-gates kernel: out[m,n] = bias[n]
//      + sum_{tap,k} srcA[pos_A(m,tap), k] * WtA[tap,k,n]     (pad = padA)
//      + sum_{tap,k} srcB[pos_B(m,tap), k] * WtB[tap,k,n]     (pad = 1, SAME)
// m indexes (b, oy, ox) over OH x OW output grid. GEMM-tiled:
// BM=128, BN=64, BK=16, 256 threads, 8x4 register tile per thread.
// ---------------------------------------------------------------------------
#define BM 128
#define BN 64
#define BK 16

__global__ __launch_bounds__(256)
void conv_gates_kernel(
    const float* __restrict__ srcA, int HA, int WA, int CA, int padA, long sAb,
    const float* __restrict__ WtA,
    const float* __restrict__ srcB, int CB, long sBb,
    const float* __restrict__ WtB,
    const float* __restrict__ bias,
    float* __restrict__ out, int OH, int OW, int N, int M)
{
    __shared__ __align__(16) float As[BK][BM];
    __shared__ __align__(16) float Bs[BK][BN];

    const int m0 = blockIdx.x * BM;
    const int n0 = blockIdx.y * BN;
    const int tid = threadIdx.x;
    const int tx = tid & 15;          // 0..15 -> N
    const int ty = tid >> 4;          // 0..15 -> M

    // A-load assignment: thread -> (m_local, 8 consecutive k)
    const int a_m = tid >> 1;         // 0..127
    const int a_k = (tid & 1) * 8;    // 0 or 8
    // B-load assignment
    const int b_k = tid >> 4;         // 0..15
    const int b_n = (tid & 15) * 4;   // 0..60

    float acc[8][4];
#pragma unroll
    for (int i = 0; i < 8; ++i)
#pragma unroll
        for (int j = 0; j < 4; ++j) acc[i][j] = 0.f;

    // decode spatial position for this thread's A row
    const int gm = m0 + a_m;
    const bool mvalid = (gm < M);
    int pb = 0, py = 0, px = 0;
    if (mvalid) {
        int r = gm;
        px = r % OW; r /= OW;
        py = r % OH; pb = r / OH;
    }

    for (int grp = 0; grp < 2; ++grp) {
        const float* src; const float* Wt;
        int C, pad, H, W; long sb;
        if (grp == 0) { src = srcA; Wt = WtA; C = CA; pad = padA; H = HA; W = WA; sb = sAb; }
        else {
            if (srcB == nullptr) break;
            src = srcB; Wt = WtB; C = CB; pad = 1; H = OH; W = OW; sb = sBb;
        }

        for (int tap = 0; tap < 9; ++tap) {
            const int dy = tap / 3, dx = tap % 3;
            const int y = py + dy - pad;
            const int x = px + dx - pad;
            const bool inb = mvalid && y >= 0 && y < H && x >= 0 && x < W;
            const float* sp = inb ? (src + (long)pb * sb + ((long)y * W + x) * C) : nullptr;

            for (int k0 = 0; k0 < C; k0 += BK) {
                // ---- load A tile (k-major) ----
                if (C - k0 >= BK) {
                    float4 v0, v1;
                    if (inb) {
                        v0 = *(const float4*)(sp + k0 + a_k);
                        v1 = *(const float4*)(sp + k0 + a_k + 4);
                    } else {
                        v0 = make_float4(0.f, 0.f, 0.f, 0.f);
                        v1 = v0;
                    }
                    As[a_k + 0][a_m] = v0.x; As[a_k + 1][a_m] = v0.y;
                    As[a_k + 2][a_m] = v0.z; As[a_k + 3][a_m] = v0.w;
                    As[a_k + 4][a_m] = v1.x; As[a_k + 5][a_m] = v1.y;
                    As[a_k + 6][a_m] = v1.z; As[a_k + 7][a_m] = v1.w;
                } else {
#pragma unroll
                    for (int s = 0; s < 8; ++s) {
                        int k = k0 + a_k + s;
                        As[a_k + s][a_m] = (inb && k < C) ? sp[k] : 0.f;
                    }
                }
                // ---- load B tile ----
                {
                    int k = k0 + b_k;
                    float4 v;
                    if (k < C) v = *(const float4*)(Wt + (long)(tap * C + k) * N + n0 + b_n);
                    else       v = make_float4(0.f, 0.f, 0.f, 0.f);
                    *(float4*)&Bs[b_k][b_n] = v;
                }
                __syncthreads();

#pragma unroll
                for (int kk = 0; kk < BK; ++kk) {
                    float4 a0 = *(const float4*)&As[kk][ty * 8];
                    float4 a1 = *(const float4*)&As[kk][ty * 8 + 4];
                    float4 bv = *(const float4*)&Bs[kk][tx * 4];
                    float av[8] = {a0.x, a0.y, a0.z, a0.w, a1.x, a1.y, a1.z, a1.w};
                    float bb[4] = {bv.x, bv.y, bv.z, bv.w};
#pragma unroll
                    for (int i = 0; i < 8; ++i)
#pragma unroll
                        for (int j = 0; j < 4; ++j)
                            acc[i][j] = fmaf(av[i], bb[j], acc[i][j]);
                }
                __syncthreads();
            }
        }
    }

    // writeback (+bias)
#pragma unroll
    for (int i = 0; i < 8; ++i) {
        int wm = m0 + ty * 8 + i;
        if (wm < M) {
            float* op = out + (long)wm * N + n0 + tx * 4;
            const float* bp = bias + n0 + tx * 4;
#pragma unroll
            for (int j = 0; j < 4; ++j) op[j] = acc[i][j] + bp[j];
        }
    }
}

// ---------------------------------------------------------------------------
// LSTM pointwise update. gates layout [m][4F] with gate order i,f,g,o.
// ---------------------------------------------------------------------------
__device__ __forceinline__ float sigmoidf_(float x) {
    return 1.f / (1.f + expf(-x));
}

__global__ void lstm_update_kernel(const float* __restrict__ gates,
                                   float* __restrict__ h, float* __restrict__ c,
                                   int M, int F)
{
    int idx = blockIdx.x * blockDim.x + threadIdx.x;
    if (idx >= M * F) return;
    int m = idx / F, f = idx % F;
    const float* g = gates + (long)m * 4 * F;
    float gi = sigmoidf_(g[f]);
    float gf = sigmoidf_(g[F + f]);
    float gg = tanhf(g[2 * F + f]);
    float go = sigmoidf_(g[3 * F + f]);
    float cn = gf * c[idx] + gi * gg;
    c[idx] = cn;
    h[idx] = go * tanhf(cn);
}

// ---------------------------------------------------------------------------
// Simple dense (last-axis matmul) with optional relu.
// ---------------------------------------------------------------------------
__global__ void dense_relu_kernel(const float* __restrict__ in,
                                  const float* __restrict__ W,
                                  const float* __restrict__ bias,
                                  float* __restrict__ out,
                                  int M, int K, int N, int do_relu)
{
    int idx = blockIdx.x * blockDim.x + threadIdx.x;
    if (idx >= M * N) return;
    int m = idx / N, n = idx % N;
    const float* ip = in + (long)m * K;
    float s = bias[n];
    for (int k = 0; k < K; ++k) s = fmaf(ip[k], W[k * N + n], s);
    if (do_relu) s = fmaxf(s, 0.f);
    out[idx] = s;
}

// ---------------------------------------------------------------------------
// Final: implicit concat (rows 0..27 = dense head, 28 = t, 29 = loc), then
// relu(v @ Wf1 + bf1) @ Wf2 + bf2 -> one scalar per (b,r,w).
// One 64-thread block per output element.
// ---------------------------------------------------------------------------
__global__ void final_fc_kernel(const float* __restrict__ dh,
                                const float* __restrict__ tin,
                                const float* __restrict__ locin,
                                const float* __restrict__ Wf1,
                                const float* __restrict__ bf1,
                                const float* __restrict__ Wf2,
                                const float* __restrict__ bf2,
                                float* __restrict__ out)
{
    int blk = blockIdx.x;              // = (b*30 + r)*28 + w
    int w = blk % 28;
    int r = (blk / 28) % 30;
    int b = blk / (28 * 30);

    __shared__ float v[64];
    __shared__ float red[64];
    int j = threadIdx.x;

    const float* src;
    if (r < 28)       src = dh    + (((long)(b * 28 + r)) * 28 + w) * 64;
    else if (r == 28) src = tin   + ((long)b * 28 + w) * 64;
    else              src = locin + ((long)b * 28 + w) * 64;
    v[j] = src[j];
    __syncthreads();

    float s = bf1[j];
#pragma unroll
    for (int k = 0; k < 64; ++k) s = fmaf(v[k], Wf1[k * 64 + j], s);
    s = fmaxf(s, 0.f) * Wf2[j];
    red[j] = s;
    __syncthreads();
    for (int off = 32; off > 0; off >>= 1) {
        if (j < off) red[j] += red[j + off];
        __syncthreads();
    }
    if (j == 0) out[blk] = red[0] + bf2[0];
}

// ---------------------------------------------------------------------------
extern "C" void kernel_launch(void* const* d_in, const int* in_sizes, int n_in,
                              void* d_out, int out_size)
{
    const float* x   = (const float*)d_in[0];
    const float* tt  = (const float*)d_in[1];
    const float* loc = (const float*)d_in[2];
    const float* Wx1 = (const float*)d_in[3];
    const float* Wh1 = (const float*)d_in[4];
    const float* b1  = (const float*)d_in[5];
    const float* Wx2 = (const float*)d_in[6];
    const float* Wh2 = (const float*)d_in[7];
    const float* b2  = (const float*)d_in[8];
    const float* Wd1 = (const float*)d_in[9];
    const float* bd1 = (const float*)d_in[10];
    const float* Wd2 = (const float*)d_in[11];
    const float* bd2 = (const float*)d_in[12];
    const float* Wf1 = (const float*)d_in[13];
    const float* bf1 = (const float*)d_in[14];
    const float* Wf2 = (const float*)d_in[15];
    const float* bf2 = (const float*)d_in[16];
    float* out = (float*)d_out;

    float *h1, *c1, *h2, *c2, *gates1, *gates2, *dh;
    cudaGetSymbolAddress((void**)&h1, g_h1);
    cudaGetSymbolAddress((void**)&c1, g_c1);
    cudaGetSymbolAddress((void**)&h2, g_h2);
    cudaGetSymbolAddress((void**)&c2, g_c2);
    cudaGetSymbolAddress((void**)&gates1, g_gates1);
    cudaGetSymbolAddress((void**)&gates2, g_gates2);
    cudaGetSymbolAddress((void**)&dh, g_dh);

    zero_state_kernel<<<1024, 256>>>();

    const int M1 = 8 * 30 * 30;   // 7200
    const int M2 = 8 * 28 * 28;   // 6272

    for (int ts = 0; ts < 10; ++ts) {
        // L1 gates: input conv (x_t, VALID, Cin=1) + recurrent conv (h1, SAME, C=256)
        conv_gates_kernel<<<dim3((M1 + BM - 1) / BM, 1024 / BN), 256>>>(
            x + (long)ts * 32 * 32, 32, 32, 1, 0, (long)10 * 32 * 32, Wx1,
            h1, 256, (long)30 * 30 * 256, Wh1,
            b1, gates1, 30, 30, 1024, M1);
        lstm_update_kernel<<<(M1 * 256 + 255) / 256, 256>>>(gates1, h1, c1, M1, 256);

        // L2 gates: input conv (h1, VALID, C=256) + recurrent conv (h2, SAME, C=128)
        conv_gates_kernel<<<dim3((M2 + BM - 1) / BM, 512 / BN), 256>>>(
            h1, 30, 30, 256, 0, (long)30 * 30 * 256, Wx2,
            h2, 128, (long)28 * 28 * 128, Wh2,
            b2, gates2, 28, 28, 512, M2);
        lstm_update_kernel<<<(M2 * 128 + 255) / 256, 256>>>(gates2, h2, c2, M2, 128);
    }

    // Dense head: 128 -> 256 relu -> 64 relu (reuse gates2 as scratch for the 256-wide)
    dense_relu_kernel<<<(M2 * 256 + 255) / 256, 256>>>(h2, Wd1, bd1, gates2, M2, 128, 256, 1);
    dense_relu_kernel<<<(M2 * 64 + 255) / 256, 256>>>(gates2, Wd2, bd2, dh, M2, 256, 64, 1);

    // Concat + FC head
    final_fc_kernel<<<8 * 30 * 28, 64>>>(dh, tt, loc, Wf1, bf1, Wf2, bf2, out);
}

// round 2
// speedup vs baseline: 1.7848x; 1.7848x over previous
#include <cuda_runtime.h>
#include <cuda_bf16.h>
#include <math.h>

// ---------------------------------------------------------------------------
// Q6Model: 2-layer ConvLSTM (T=10) + dense head + concat + FC head
// Round 2: conv-gates GEMM on tensor cores (mma.sync m16n8k8 tf32).
// ---------------------------------------------------------------------------

#define H1N (8*30*30*256)
#define H2N (8*28*28*128)

__device__ float g_h1[H1N];
__device__ float g_c1[H1N];
__device__ float g_h2[H2N];
__device__ float g_c2[H2N];
__device__ float g_gates1[8*30*30*1024];
__device__ float g_gates2[8*28*28*512];
__device__ float g_dh[8*28*28*64];

__global__ void zero_state_kernel() {
    int i = blockIdx.x * blockDim.x + threadIdx.x;
    int stride = gridDim.x * blockDim.x;
    for (int k = i; k < H1N; k += stride) { g_h1[k] = 0.f; g_c1[k] = 0.f; }
    for (int k = i; k < H2N; k += stride) { g_h2[k] = 0.f; g_c2[k] = 0.f; }
}

__device__ __forceinline__ unsigned f2tf32(float f) {
    unsigned r;
    asm("cvt.rna.tf32.f32 %0, %1;" : "=r"(r) : "f"(f));
    return r;
}

__device__ __forceinline__ void mma_tf32(float* d, const unsigned* a, const unsigned* b) {
    asm volatile(
        "mma.sync.aligned.m16n8k8.row.col.f32.tf32.tf32.f32 "
        "{%0,%1,%2,%3}, {%4,%5,%6,%7}, {%8,%9}, {%0,%1,%2,%3};\n"
        : "+f"(d[0]), "+f"(d[1]), "+f"(d[2]), "+f"(d[3])
        : "r"(a[0]), "r"(a[1]), "r"(a[2]), "r"(a[3]), "r"(b[0]), "r"(b[1]));
}

// ---------------------------------------------------------------------------
// Fused conv-gates GEMM (tensor core):
//   out[m,n] = bias[n] + sum_{tap,k} srcA[posA(m,tap),k]*WtA[tap,k,n]  (pad=padA)
//            +           sum_{tap,k} srcB[posB(m,tap),k]*WtB[tap,k,n]  (pad=1)
// Block tile: BM=128 x BN=64, BK=32. 256 threads = 8 warps (4M x 2N),
// warp tile 32x32 via m16n8k8 tf32 (2 m-frags x 4 n-frags).
// SMEM k-major, padded +8 for conflict-free fragment gathers.
// ---------------------------------------------------------------------------
#define BM 128
#define BN 64
#define BK 32
#define LDA 136
#define LDB 72

__global__ __launch_bounds__(256)
void conv_gates_kernel(
    const float* __restrict__ srcA, int HA, int WA, int CA, int padA, long sAb,
    const float* __restrict__ WtA,
    const float* __restrict__ srcB, int CB, long sBb,
    const float* __restrict__ WtB,
    const float* __restrict__ bias,
    float* __restrict__ out, int OH, int OW, int N, int M)
{
    __shared__ unsigned As[BK][LDA];
    __shared__ unsigned Bs[BK][LDB];

    const int m0 = blockIdx.x * BM;
    const int n0 = blockIdx.y * BN;
    const int tid = threadIdx.x;

    // staging assignments
    const int a_m  = tid >> 1;          // 0..127 (row within tile)
    const int a_k0 = (tid & 1) * 16;    // 0 or 16
    const int b_k  = tid >> 3;          // 0..31
    const int b_n  = (tid & 7) * 8;     // 0..56

    // mma assignments
    const int wid  = tid >> 5;
    const int lane = tid & 31;
    const int wm   = (wid & 3) * 32;    // warp M base (0..96)
    const int wn   = (wid >> 2) * 32;   // warp N base (0 or 32)
    const int g    = lane >> 2;         // 0..7
    const int tg   = lane & 3;          // 0..3

    float acc[2][4][4];
#pragma unroll
    for (int mi = 0; mi < 2; ++mi)
#pragma unroll
        for (int ni = 0; ni < 4; ++ni)
#pragma unroll
            for (int r = 0; r < 4; ++r) acc[mi][ni][r] = 0.f;

    // spatial decode for this thread's staging row
    const int gm = m0 + a_m;
    const bool mvalid = (gm < M);
    int pb = 0, py = 0, px = 0;
    if (mvalid) {
        int r = gm;
        px = r % OW; r /= OW;
        py = r % OH; pb = r / OH;
    }

    for (int grp = 0; grp < 2; ++grp) {
        const float* src; const float* Wt;
        int C, pad, H, W; long sb;
        if (grp == 0) { src = srcA; Wt = WtA; C = CA; pad = padA; H = HA; W = WA; sb = sAb; }
        else          { src = srcB; Wt = WtB; C = CB; pad = 1;    H = OH; W = OW; sb = sBb; }

        for (int tap = 0; tap < 9; ++tap) {
            const int dy = tap / 3, dx = tap % 3;
            const int y = py + dy - pad;
            const int x = px + dx - pad;
            const bool inb = mvalid && y >= 0 && y < H && x >= 0 && x < W;
            const float* sp = inb ? (src + (long)pb * sb + ((long)y * W + x) * C) : nullptr;

            for (int K0 = 0; K0 < C; K0 += BK) {
                // ---- stage A (k-major, tf32) ----
                if (K0 + BK <= C) {
                    if (inb) {
#pragma unroll
                        for (int q = 0; q < 4; ++q) {
                            float4 v = *(const float4*)(sp + K0 + a_k0 + q * 4);
                            As[a_k0 + q * 4 + 0][a_m] = f2tf32(v.x);
                            As[a_k0 + q * 4 + 1][a_m] = f2tf32(v.y);
                            As[a_k0 + q * 4 + 2][a_m] = f2tf32(v.z);
                            As[a_k0 + q * 4 + 3][a_m] = f2tf32(v.w);
                        }
                    } else {
#pragma unroll
                        for (int j = 0; j < 16; ++j) As[a_k0 + j][a_m] = 0u;
                    }
                } else {
#pragma unroll
                    for (int j = 0; j < 16; ++j) {
                        int k = K0 + a_k0 + j;
                        float v = (inb && k < C) ? sp[k] : 0.f;
                        As[a_k0 + j][a_m] = f2tf32(v);
                    }
                }
                // ---- stage B ----
                {
                    int k = K0 + b_k;
                    if (k < C) {
                        const float* wp = Wt + (long)(tap * C + k) * N + n0 + b_n;
                        float4 v0 = *(const float4*)(wp);
                        float4 v1 = *(const float4*)(wp + 4);
                        Bs[b_k][b_n + 0] = f2tf32(v0.x); Bs[b_k][b_n + 1] = f2tf32(v0.y);
                        Bs[b_k][b_n + 2] = f2tf32(v0.z); Bs[b_k][b_n + 3] = f2tf32(v0.w);
                        Bs[b_k][b_n + 4] = f2tf32(v1.x); Bs[b_k][b_n + 5] = f2tf32(v1.y);
                        Bs[b_k][b_n + 6] = f2tf32(v1.z); Bs[b_k][b_n + 7] = f2tf32(v1.w);
                    } else {
#pragma unroll
                        for (int j = 0; j < 8; ++j) Bs[b_k][b_n + j] = 0u;
                    }
                }
                __syncthreads();

                // ---- tensor-core compute: 4 k8 steps ----
#pragma unroll
                for (int kk = 0; kk < BK; kk += 8) {
                    unsigned a[2][4];
#pragma unroll
                    for (int mi = 0; mi < 2; ++mi) {
                        int r = wm + mi * 16 + g;
                        a[mi][0] = As[kk + tg][r];
                        a[mi][1] = As[kk + tg][r + 8];
                        a[mi][2] = As[kk + 4 + tg][r];
                        a[mi][3] = As[kk + 4 + tg][r + 8];
                    }
                    unsigned b[4][2];
#pragma unroll
                    for (int ni = 0; ni < 4; ++ni) {
                        int cc = wn + ni * 8 + g;
                        b[ni][0] = Bs[kk + tg][cc];
                        b[ni][1] = Bs[kk + 4 + tg][cc];
                    }
#pragma unroll
                    for (int mi = 0; mi < 2; ++mi)
#pragma unroll
                        for (int ni = 0; ni < 4; ++ni)
                            mma_tf32(acc[mi][ni], a[mi], b[ni]);
                }
                __syncthreads();
            }
        }
    }

    // ---- writeback (+bias) ----
#pragma unroll
    for (int mi = 0; mi < 2; ++mi) {
#pragma unroll
        for (int ni = 0; ni < 4; ++ni) {
            int col = n0 + wn + ni * 8 + 2 * tg;
            float b0 = bias[col], b1 = bias[col + 1];
            int row0 = m0 + wm + mi * 16 + g;
            int row1 = row0 + 8;
            if (row0 < M) {
                float2 v; v.x = acc[mi][ni][0] + b0; v.y = acc[mi][ni][1] + b1;
                *(float2*)(out + (long)row0 * N + col) = v;
            }
            if (row1 < M) {
                float2 v; v.x = acc[mi][ni][2] + b0; v.y = acc[mi][ni][3] + b1;
                *(float2*)(out + (long)row1 * N + col) = v;
            }
        }
    }
}

// ---------------------------------------------------------------------------
// LSTM pointwise update (float4-vectorized). gates layout [m][4F], order i,f,g,o.
// ---------------------------------------------------------------------------
__device__ __forceinline__ float sigmoidf_(float x) {
    return 1.f / (1.f + expf(-x));
}

__global__ void lstm_update_kernel(const float* __restrict__ gates,
                                   float* __restrict__ h, float* __restrict__ c,
                                   int M, int F)
{
    int idx = blockIdx.x * blockDim.x + threadIdx.x;   // over M*F/4
    int total = M * F / 4;
    if (idx >= total) return;
    int m = idx / (F / 4);
    int f4 = (idx % (F / 4)) * 4;
    const float* gp = gates + (long)m * 4 * F;
    float4 gi = *(const float4*)(gp + f4);
    float4 gf = *(const float4*)(gp + F + f4);
    float4 gg = *(const float4*)(gp + 2 * F + f4);
    float4 go = *(const float4*)(gp + 3 * F + f4);
    float4 cv = *(const float4*)(c + (long)m * F + f4);
    float4 cn, hn;
    cn.x = sigmoidf_(gf.x) * cv.x + sigmoidf_(gi.x) * tanhf(gg.x);
    cn.y = sigmoidf_(gf.y) * cv.y + sigmoidf_(gi.y) * tanhf(gg.y);
    cn.z = sigmoidf_(gf.z) * cv.z + sigmoidf_(gi.z) * tanhf(gg.z);
    cn.w = sigmoidf_(gf.w) * cv.w + sigmoidf_(gi.w) * tanhf(gg.w);
    hn.x = sigmoidf_(go.x) * tanhf(cn.x);
    hn.y = sigmoidf_(go.y) * tanhf(cn.y);
    hn.z = sigmoidf_(go.z) * tanhf(cn.z);
    hn.w = sigmoidf_(go.w) * tanhf(cn.w);
    *(float4*)(c + (long)m * F + f4) = cn;
    *(float4*)(h + (long)m * F + f4) = hn;
}

// ---------------------------------------------------------------------------
__global__ void dense_relu_kernel(const float* __restrict__ in,
                                  const float* __restrict__ W,
                                  const float* __restrict__ bias,
                                  float* __restrict__ out,
                                  int M, int K, int N, int do_relu)
{
    int idx = blockIdx.x * blockDim.x + threadIdx.x;
    if (idx >= M * N) return;
    int m = idx / N, n = idx % N;
    const float* ip = in + (long)m * K;
    float s = bias[n];
    for (int k = 0; k < K; ++k) s = fmaf(ip[k], W[k * N + n], s);
    if (do_relu) s = fmaxf(s, 0.f);
    out[idx] = s;
}

// ---------------------------------------------------------------------------
__global__ void final_fc_kernel(const float* __restrict__ dh,
                                const float* __restrict__ tin,
                                const float* __restrict__ locin,
                                const float* __restrict__ Wf1,
                                const float* __restrict__ bf1,
                                const float* __restrict__ Wf2,
                                const float* __restrict__ bf2,
                                float* __restrict__ out)
{
    int blk = blockIdx.x;              // = (b*30 + r)*28 + w
    int w = blk % 28;
    int r = (blk / 28) % 30;
    int b = blk / (28 * 30);

    __shared__ float v[64];
    __shared__ float red[64];
    int j = threadIdx.x;

    const float* src;
    if (r < 28)       src = dh    + (((long)(b * 28 + r)) * 28 + w) * 64;
    else if (r == 28) src = tin   + ((long)b * 28 + w) * 64;
    else              src = locin + ((long)b * 28 + w) * 64;
    v[j] = src[j];
    __syncthreads();

    float s = bf1[j];
#pragma unroll
    for (int k = 0; k < 64; ++k) s = fmaf(v[k], Wf1[k * 64 + j], s);
    s = fmaxf(s, 0.f) * Wf2[j];
    red[j] = s;
    __syncthreads();
    for (int off = 32; off > 0; off >>= 1) {
        if (j < off) red[j] += red[j + off];
        __syncthreads();
    }
    if (j == 0) out[blk] = red[0] + bf2[0];
}

// ---------------------------------------------------------------------------
extern "C" void kernel_launch(void* const* d_in, const int* in_sizes, int n_in,
                              void* d_out, int out_size)
{
    const float* x   = (const float*)d_in[0];
    const float* tt  = (const float*)d_in[1];
    const float* loc = (const float*)d_in[2];
    const float* Wx1 = (const float*)d_in[3];
    const float* Wh1 = (const float*)d_in[4];
    const float* b1  = (const float*)d_in[5];
    const float* Wx2 = (const float*)d_in[6];
    const float* Wh2 = (const float*)d_in[7];
    const float* b2  = (const float*)d_in[8];
    const float* Wd1 = (const float*)d_in[9];
    const float* bd1 = (const float*)d_in[10];
    const float* Wd2 = (const float*)d_in[11];
    const float* bd2 = (const float*)d_in[12];
    const float* Wf1 = (const float*)d_in[13];
    const float* bf1 = (const float*)d_in[14];
    const float* Wf2 = (const float*)d_in[15];
    const float* bf2 = (const float*)d_in[16];
    float* out = (float*)d_out;

    float *h1, *c1, *h2, *c2, *gates1, *gates2, *dh;
    cudaGetSymbolAddress((void**)&h1, g_h1);
    cudaGetSymbolAddress((void**)&c1, g_c1);
    cudaGetSymbolAddress((void**)&h2, g_h2);
    cudaGetSymbolAddress((void**)&c2, g_c2);
    cudaGetSymbolAddress((void**)&gates1, g_gates1);
    cudaGetSymbolAddress((void**)&gates2, g_gates2);
    cudaGetSymbolAddress((void**)&dh, g_dh);

    zero_state_kernel<<<1024, 256>>>();

    const int M1 = 8 * 30 * 30;   // 7200
    const int M2 = 8 * 28 * 28;   // 6272

    for (int ts = 0; ts < 10; ++ts) {
        conv_gates_kernel<<<dim3((M1 + BM - 1) / BM, 1024 / BN), 256>>>(
            x + (long)ts * 32 * 32, 32, 32, 1, 0, (long)10 * 32 * 32, Wx1,
            h1, 256, (long)30 * 30 * 256, Wh1,
            b1, gates1, 30, 30, 1024, M1);
        lstm_update_kernel<<<(M1 * 256 / 4 + 255) / 256, 256>>>(gates1, h1, c1, M1, 256);

        conv_gates_kernel<<<dim3((M2 + BM - 1) / BM, 512 / BN), 256>>>(
            h1, 30, 30, 256, 0, (long)30 * 30 * 256, Wx2,
            h2, 128, (long)28 * 28 * 128, Wh2,
            b2, gates2, 28, 28, 512, M2);
        lstm_update_kernel<<<(M2 * 128 / 4 + 255) / 256, 256>>>(gates2, h2, c2, M2, 128);
    }

    dense_relu_kernel<<<(M2 * 256 + 255) / 256, 256>>>(h2, Wd1, bd1, gates2, M2, 128, 256, 1);
    dense_relu_kernel<<<(M2 * 64 + 255) / 256, 256>>>(gates2, Wd2, bd2, dh, M2, 256, 64, 1);

    final_fc_kernel<<<8 * 30 * 28, 64>>>(dh, tt, loc, Wf1, bf1, Wf2, bf2, out);
}

// round 4
// speedup vs baseline: 2.2208x; 1.2443x over previous
#include <cuda_runtime.h>
#include <cuda_bf16.h>
#include <cstdint>
#include <math.h>

// ---------------------------------------------------------------------------
// Q6Model: 2-layer ConvLSTM (T=10) + dense head + concat + FC head
// Round 4 (= Round 3 + build fix): BN=128 / warp 64x32 tf32 mma, cp.async
// double-buffered pipeline, tf32 pre-rounding, L1 x-conv as fp32 epilogue.
// ---------------------------------------------------------------------------

#define H1N (8*30*30*256)
#define H2N (8*28*28*128)

__device__ float g_h1[H1N];
__device__ float g_c1[H1N];
__device__ float g_h2[H2N];
__device__ float g_c2[H2N];
__device__ float g_gates1[8*30*30*1024];
__device__ float g_gates2[8*28*28*512];
__device__ float g_dh[8*28*28*64];
// tf32-rounded weights
__device__ float g_Wh1r[9*256*1024];
__device__ float g_Wx2r[9*256*512];
__device__ float g_Wh2r[9*128*512];

__device__ __forceinline__ unsigned f2tf32(float f) {
    unsigned r;
    asm("cvt.rna.tf32.f32 %0, %1;" : "=r"(r) : "f"(f));
    return r;
}
__device__ __forceinline__ float tf32r(float f) { return __uint_as_float(f2tf32(f)); }

__global__ void zero_state_kernel() {
    int i = blockIdx.x * blockDim.x + threadIdx.x;
    int stride = gridDim.x * blockDim.x;
    for (int k = i; k < H1N; k += stride) { g_h1[k] = 0.f; g_c1[k] = 0.f; }
    for (int k = i; k < H2N; k += stride) { g_h2[k] = 0.f; g_c2[k] = 0.f; }
}

__global__ void round_weights_kernel(const float* __restrict__ in, float* __restrict__ out, int n) {
    int i = blockIdx.x * blockDim.x + threadIdx.x;
    int stride = gridDim.x * blockDim.x;
    for (int k = i; k < n; k += stride) out[k] = tf32r(in[k]);
}

__device__ __forceinline__ void mma_tf32(float* d, const unsigned* a, const unsigned* b) {
    asm volatile(
        "mma.sync.aligned.m16n8k8.row.col.f32.tf32.tf32.f32 "
        "{%0,%1,%2,%3}, {%4,%5,%6,%7}, {%8,%9}, {%0,%1,%2,%3};\n"
        : "+f"(d[0]), "+f"(d[1]), "+f"(d[2]), "+f"(d[3])
        : "r"(a[0]), "r"(a[1]), "r"(a[2]), "r"(a[3]), "r"(b[0]), "r"(b[1]));
}

__device__ __forceinline__ void cp16(unsigned int dst, const float* src, int sz) {
    asm volatile("cp.async.cg.shared.global [%0], [%1], 16, %2;"
                 :: "r"(dst), "l"(src), "r"(sz));
}

// ---------------------------------------------------------------------------
// Fused conv-gates GEMM, tensor core, pipelined.
//   out[m,n] = bias[n] + sum_{grp,tap,k} src[pos(m,tap),k]*Wt[tap,k,n]
//            + (useX: fp32 epilogue 3x3 conv with CA=1 input srcA/WtA)
// BM=128, BN=128, BK=32, 256 threads = 8 warps (2M x 4N), warp tile 64x32.
// A staged m-major [128][36], B staged k-major [32][136]; double-buffered
// via cp.async (2 x 35840 B dynamic SMEM).
// ---------------------------------------------------------------------------
#define BM 128
#define BN 128
#define BK 32
#define LDA 36
#define LDB 136
#define A_WORDS (BM*LDA)                 // 4608
#define B_WORDS (BK*LDB)                 // 4352
#define STAGE_WORDS (A_WORDS + B_WORDS)  // 8960
#define CONV_SMEM_BYTES (2*STAGE_WORDS*4)

__global__ __launch_bounds__(256)
void conv_gates_kernel(
    const float* __restrict__ srcA, int CA, int HA, int WA, long sAb, int padA,
    const float* __restrict__ WtA, int kt0,
    const float* __restrict__ srcB, int CB, long sBb,
    const float* __restrict__ WtB, int kt1,
    int useX,
    const float* __restrict__ bias,
    float* __restrict__ out, int OH, int OW, int N, int M)
{
    extern __shared__ float smem[];
    unsigned int smem_u = (unsigned int)__cvta_generic_to_shared(smem);

    const int tid = threadIdx.x;
    const int m0 = blockIdx.x * BM;
    const int n0 = blockIdx.y * BN;

    const int wid = tid >> 5, lane = tid & 31;
    const int wm = (wid >> 2) * 64;       // 2 warp rows
    const int wn = (wid & 3) * 32;        // 4 warp cols
    const int g = lane >> 2, tg = lane & 3;

    // staging coords
    const int am = tid >> 1;              // A row 0..127
    const int khalf = (tid & 1) * 16;     // k 0..15 / 16..31
    const int bk = tid >> 3;              // B k-row 0..31
    const int bn = (tid & 7) * 16;        // B col chunk

    int s_pb = 0, s_py = 0, s_px = 0;
    bool s_valid;
    {
        int gm = m0 + am;
        s_valid = gm < M;
        int r = s_valid ? gm : 0;
        s_px = r % OW; r /= OW;
        s_py = r % OH; s_pb = r / OH;
    }

    const int nt0 = 9 * kt0;
    const int ntiles = nt0 + 9 * kt1;

    float acc[4][4][4];
#pragma unroll
    for (int mi = 0; mi < 4; ++mi)
#pragma unroll
        for (int ni = 0; ni < 4; ++ni)
#pragma unroll
            for (int r = 0; r < 4; ++r) acc[mi][ni][r] = 0.f;

    auto stage = [&](int t, int buf) {
        int tap, K0, C, H, W, pad;
        long sb;
        const float *src, *Wt;
        if (t < nt0) {
            tap = t / kt0; K0 = (t - tap * kt0) * BK;
            src = srcA; Wt = WtA; C = CA; H = HA; W = WA; sb = sAb; pad = padA;
        } else {
            int u = t - nt0;
            tap = u / kt1; K0 = (u - tap * kt1) * BK;
            src = srcB; Wt = WtB; C = CB; H = OH; W = OW; sb = sBb; pad = 1;
        }
        int y = s_py + tap / 3 - pad;
        int x = s_px + tap % 3 - pad;
        bool ok = s_valid && ((unsigned)y < (unsigned)H) && ((unsigned)x < (unsigned)W);
        const float* sp = ok ? src + (long)s_pb * sb + ((long)y * W + x) * C + K0 + khalf
                             : src;
        int sz = ok ? 16 : 0;
        unsigned int da = smem_u + (unsigned int)(buf * STAGE_WORDS + am * LDA + khalf) * 4u;
#pragma unroll
        for (int q = 0; q < 4; ++q) cp16(da + q * 16, sp + q * 4, sz);
        const float* wp = Wt + (long)(tap * C + K0 + bk) * N + n0 + bn;
        unsigned int db = smem_u + (unsigned int)(buf * STAGE_WORDS + A_WORDS + bk * LDB + bn) * 4u;
#pragma unroll
        for (int q = 0; q < 4; ++q) cp16(db + q * 16, wp + q * 4, 16);
    };

    auto compute = [&](int buf) {
        const float* As = smem + buf * STAGE_WORDS;
        const float* Bs = As + A_WORDS;
#pragma unroll
        for (int kk = 0; kk < BK; kk += 8) {
            unsigned a[4][4];
#pragma unroll
            for (int mi = 0; mi < 4; ++mi) {
                const float* ap = As + (wm + mi * 16 + g) * LDA + kk + tg;
                a[mi][0] = __float_as_uint(ap[0]);
                a[mi][1] = __float_as_uint(ap[8 * LDA]);
                a[mi][2] = __float_as_uint(ap[4]);
                a[mi][3] = __float_as_uint(ap[8 * LDA + 4]);
            }
            unsigned b[4][2];
#pragma unroll
            for (int ni = 0; ni < 4; ++ni) {
                const float* bp = Bs + (kk + tg) * LDB + wn + ni * 8 + g;
                b[ni][0] = __float_as_uint(bp[0]);
                b[ni][1] = __float_as_uint(bp[4 * LDB]);
            }
#pragma unroll
            for (int mi = 0; mi < 4; ++mi)
#pragma unroll
                for (int ni = 0; ni < 4; ++ni)
                    mma_tf32(acc[mi][ni], a[mi], b[ni]);
        }
    };

    // ---- pipelined main loop ----
    stage(0, 0);
    asm volatile("cp.async.commit_group;");
    for (int t = 0; t < ntiles; ++t) {
        if (t + 1 < ntiles) {
            stage(t + 1, (t + 1) & 1);
            asm volatile("cp.async.commit_group;");
            asm volatile("cp.async.wait_group 1;");
        } else {
            asm volatile("cp.async.wait_group 0;");
        }
        __syncthreads();
        compute(t & 1);
        __syncthreads();
    }

    // ---- fp32 epilogue for the C=1 input conv (layer 1 only) ----
    if (useX) {
        int epb[8], epy[8], epx[8];
        bool ev[8];
#pragma unroll
        for (int e = 0; e < 8; ++e) {
            int rr = m0 + wm + (e >> 1) * 16 + g + (e & 1) * 8;
            ev[e] = rr < M;
            int r2 = ev[e] ? rr : 0;
            epx[e] = r2 % OW; r2 /= OW;
            epy[e] = r2 % OH; epb[e] = r2 / OH;
        }
        for (int tap = 0; tap < 9; ++tap) {
            int dy = tap / 3, dx = tap % 3;   // VALID: pad 0
            float wv[4][2];
#pragma unroll
            for (int ni = 0; ni < 4; ++ni) {
                int col = n0 + wn + ni * 8 + 2 * tg;
                wv[ni][0] = WtA[tap * N + col];
                wv[ni][1] = WtA[tap * N + col + 1];
            }
#pragma unroll
            for (int e = 0; e < 8; ++e) if (ev[e]) {
                float xv = srcA[(long)epb[e] * sAb + (long)(epy[e] + dy) * WA + (epx[e] + dx)];
#pragma unroll
                for (int ni = 0; ni < 4; ++ni) {
                    acc[e >> 1][ni][(e & 1) * 2 + 0] = fmaf(xv, wv[ni][0], acc[e >> 1][ni][(e & 1) * 2 + 0]);
                    acc[e >> 1][ni][(e & 1) * 2 + 1] = fmaf(xv, wv[ni][1], acc[e >> 1][ni][(e & 1) * 2 + 1]);
                }
            }
        }
    }

    // ---- writeback (+bias) ----
#pragma unroll
    for (int mi = 0; mi < 4; ++mi) {
#pragma unroll
        for (int ni = 0; ni < 4; ++ni) {
            int col = n0 + wn + ni * 8 + 2 * tg;
            float b0 = bias[col], b1 = bias[col + 1];
            int r0 = m0 + wm + mi * 16 + g;
            int r1 = r0 + 8;
            if (r0 < M) {
                float2 v; v.x = acc[mi][ni][0] + b0; v.y = acc[mi][ni][1] + b1;
                *(float2*)(out + (long)r0 * N + col) = v;
            }
            if (r1 < M) {
                float2 v; v.x = acc[mi][ni][2] + b0; v.y = acc[mi][ni][3] + b1;
                *(float2*)(out + (long)r1 * N + col) = v;
            }
        }
    }
}

// ---------------------------------------------------------------------------
// LSTM pointwise update; h is written tf32-rounded so the next GEMM consumes
// exact tf32 operands via cp.async (no in-kernel cvt needed).
// ---------------------------------------------------------------------------
__device__ __forceinline__ float sigmoidf_(float x) {
    return 1.f / (1.f + expf(-x));
}

__global__ void lstm_update_kernel(const float* __restrict__ gates,
                                   float* __restrict__ h, float* __restrict__ c,
                                   int M, int F)
{
    int idx = blockIdx.x * blockDim.x + threadIdx.x;
    int total = M * F / 4;
    if (idx >= total) return;
    int m = idx / (F / 4);
    int f4 = (idx % (F / 4)) * 4;
    const float* gp = gates + (long)m * 4 * F;
    float4 gi = *(const float4*)(gp + f4);
    float4 gf = *(const float4*)(gp + F + f4);
    float4 gg = *(const float4*)(gp + 2 * F + f4);
    float4 go = *(const float4*)(gp + 3 * F + f4);
    float4 cv = *(const float4*)(c + (long)m * F + f4);
    float4 cn, hn;
    cn.x = sigmoidf_(gf.x) * cv.x + sigmoidf_(gi.x) * tanhf(gg.x);
    cn.y = sigmoidf_(gf.y) * cv.y + sigmoidf_(gi.y) * tanhf(gg.y);
    cn.z = sigmoidf_(gf.z) * cv.z + sigmoidf_(gi.z) * tanhf(gg.z);
    cn.w = sigmoidf_(gf.w) * cv.w + sigmoidf_(gi.w) * tanhf(gg.w);
    hn.x = tf32r(sigmoidf_(go.x) * tanhf(cn.x));
    hn.y = tf32r(sigmoidf_(go.y) * tanhf(cn.y));
    hn.z = tf32r(sigmoidf_(go.z) * tanhf(cn.z));
    hn.w = tf32r(sigmoidf_(go.w) * tanhf(cn.w));
    *(float4*)(c + (long)m * F + f4) = cn;
    *(float4*)(h + (long)m * F + f4) = hn;
}

// ---------------------------------------------------------------------------
__global__ void dense_relu_kernel(const float* __restrict__ in,
                                  const float* __restrict__ W,
                                  const float* __restrict__ bias,
                                  float* __restrict__ out,
                                  int M, int K, int N, int do_relu)
{
    int idx = blockIdx.x * blockDim.x + threadIdx.x;
    if (idx >= M * N) return;
    int m = idx / N, n = idx % N;
    const float* ip = in + (long)m * K;
    float s = bias[n];
    for (int k = 0; k < K; ++k) s = fmaf(ip[k], W[k * N + n], s);
    if (do_relu) s = fmaxf(s, 0.f);
    out[idx] = s;
}

// ---------------------------------------------------------------------------
__global__ void final_fc_kernel(const float* __restrict__ dh,
                                const float* __restrict__ tin,
                                const float* __restrict__ locin,
                                const float* __restrict__ Wf1,
                                const float* __restrict__ bf1,
                                const float* __restrict__ Wf2,
                                const float* __restrict__ bf2,
                                float* __restrict__ out)
{
    int blk = blockIdx.x;              // = (b*30 + r)*28 + w
    int w = blk % 28;
    int r = (blk / 28) % 30;
    int b = blk / (28 * 30);

    __shared__ float v[64];
    __shared__ float red[64];
    int j = threadIdx.x;

    const float* src;
    if (r < 28)       src = dh    + (((long)(b * 28 + r)) * 28 + w) * 64;
    else if (r == 28) src = tin   + ((long)b * 28 + w) * 64;
    else              src = locin + ((long)b * 28 + w) * 64;
    v[j] = src[j];
    __syncthreads();

    float s = bf1[j];
#pragma unroll
    for (int k = 0; k < 64; ++k) s = fmaf(v[k], Wf1[k * 64 + j], s);
    s = fmaxf(s, 0.f) * Wf2[j];
    red[j] = s;
    __syncthreads();
    for (int off = 32; off > 0; off >>= 1) {
        if (j < off) red[j] += red[j + off];
        __syncthreads();
    }
    if (j == 0) out[blk] = red[0] + bf2[0];
}

// ---------------------------------------------------------------------------
extern "C" void kernel_launch(void* const* d_in, const int* in_sizes, int n_in,
                              void* d_out, int out_size)
{
    const float* x   = (const float*)d_in[0];
    const float* tt  = (const float*)d_in[1];
    const float* loc = (const float*)d_in[2];
    const float* Wx1 = (const float*)d_in[3];
    const float* Wh1 = (const float*)d_in[4];
    const float* b1  = (const float*)d_in[5];
    const float* Wx2 = (const float*)d_in[6];
    const float* Wh2 = (const float*)d_in[7];
    const float* b2  = (const float*)d_in[8];
    const float* Wd1 = (const float*)d_in[9];
    const float* bd1 = (const float*)d_in[10];
    const float* Wd2 = (const float*)d_in[11];
    const float* bd2 = (const float*)d_in[12];
    const float* Wf1 = (const float*)d_in[13];
    const float* bf1 = (const float*)d_in[14];
    const float* Wf2 = (const float*)d_in[15];
    const float* bf2 = (const float*)d_in[16];
    float* out = (float*)d_out;

    float *h1, *c1, *h2, *c2, *gates1, *gates2, *dh, *Wh1r, *Wx2r, *Wh2r;
    cudaGetSymbolAddress((void**)&h1, g_h1);
    cudaGetSymbolAddress((void**)&c1, g_c1);
    cudaGetSymbolAddress((void**)&h2, g_h2);
    cudaGetSymbolAddress((void**)&c2, g_c2);
    cudaGetSymbolAddress((void**)&gates1, g_gates1);
    cudaGetSymbolAddress((void**)&gates2, g_gates2);
    cudaGetSymbolAddress((void**)&dh, g_dh);
    cudaGetSymbolAddress((void**)&Wh1r, g_Wh1r);
    cudaGetSymbolAddress((void**)&Wx2r, g_Wx2r);
    cudaGetSymbolAddress((void**)&Wh2r, g_Wh2r);

    cudaFuncSetAttribute(conv_gates_kernel,
                         cudaFuncAttributeMaxDynamicSharedMemorySize, CONV_SMEM_BYTES);

    zero_state_kernel<<<1024, 256>>>();
    round_weights_kernel<<<512, 256>>>(Wh1, Wh1r, 9 * 256 * 1024);
    round_weights_kernel<<<512, 256>>>(Wx2, Wx2r, 9 * 256 * 512);
    round_weights_kernel<<<512, 256>>>(Wh2, Wh2r, 9 * 128 * 512);

    const int M1 = 8 * 30 * 30;   // 7200
    const int M2 = 8 * 28 * 28;   // 6272

    for (int ts = 0; ts < 10; ++ts) {
        // L1: recurrent conv GEMM (h1, SAME, C=256) + x-conv fp32 epilogue
        conv_gates_kernel<<<dim3((M1 + BM - 1) / BM, 1024 / BN), 256, CONV_SMEM_BYTES>>>(
            x + (long)ts * 32 * 32, 1, 32, 32, (long)10 * 32 * 32, 0, Wx1, /*kt0=*/0,
            h1, 256, (long)30 * 30 * 256, Wh1r, /*kt1=*/8,
            /*useX=*/1,
            b1, gates1, 30, 30, 1024, M1);
        lstm_update_kernel<<<(M1 * 256 / 4 + 255) / 256, 256>>>(gates1, h1, c1, M1, 256);

        // L2: input conv (h1, VALID, C=256) + recurrent conv (h2, SAME, C=128)
        conv_gates_kernel<<<dim3((M2 + BM - 1) / BM, 512 / BN), 256, CONV_SMEM_BYTES>>>(
            h1, 256, 30, 30, (long)30 * 30 * 256, 0, Wx2r, /*kt0=*/8,
            h2, 128, (long)28 * 28 * 128, Wh2r, /*kt1=*/4,
            /*useX=*/0,
            b2, gates2, 28, 28, 512, M2);
        lstm_update_kernel<<<(M2 * 128 / 4 + 255) / 256, 256>>>(gates2, h2, c2, M2, 128);
    }

    dense_relu_kernel<<<(M2 * 256 + 255) / 256, 256>>>(h2, Wd1, bd1, gates2, M2, 128, 256, 1);
    dense_relu_kernel<<<(M2 * 64 + 255) / 256, 256>>>(gates2, Wd2, bd2, dh, M2, 256, 64, 1);

    final_fc_kernel<<<8 * 30 * 28, 64>>>(dh, tt, loc, Wf1, bf1, Wf2, bf2, out);
}

// round 5
// speedup vs baseline: 4.4307x; 1.9951x over previous
#include <cuda_runtime.h>
#include <cuda_bf16.h>
#include <cstdint>
#include <math.h>

// ---------------------------------------------------------------------------
// Q6Model: 2-layer ConvLSTM (T=10) + dense head + concat + FC head
// Round 5: bf16 m16n8k16 mma (fp32 accum), k-pair packed weights, bf16 h,
//          4-buffer cp.async ring w/ single sync per tile, fp32 x-epilogue.
// ---------------------------------------------------------------------------

#define H1N (8*30*30*256)
#define H2N (8*28*28*128)

__device__ __nv_bfloat16 g_h1b[H1N];
__device__ float         g_c1[H1N];
__device__ __nv_bfloat16 g_h2b[H2N];
__device__ float         g_c2[H2N];
__device__ float         g_h2f[H2N];      // fp32 copy of h2 for dense head
__device__ float g_gates1[8*30*30*1024];
__device__ float g_gates2[8*28*28*512];
__device__ float g_dh[8*28*28*64];
// packed bf16x2 weights: [tap][k/2][n], pair = (k, k+1)
__device__ unsigned g_Wh1p[9*128*1024];
__device__ unsigned g_Wx2p[9*128*512];
__device__ unsigned g_Wh2p[9*64*512];

__global__ void zero_state_kernel() {
    int i = blockIdx.x * blockDim.x + threadIdx.x;
    int stride = gridDim.x * blockDim.x;
    unsigned* h1u = (unsigned*)g_h1b;
    unsigned* h2u = (unsigned*)g_h2b;
    for (int k = i; k < H1N; k += stride) g_c1[k] = 0.f;
    for (int k = i; k < H1N / 2; k += stride) h1u[k] = 0u;
    for (int k = i; k < H2N; k += stride) g_c2[k] = 0.f;
    for (int k = i; k < H2N / 2; k += stride) h2u[k] = 0u;
}

// Pack W[tap][k][n] (fp32, row len N) -> out[tap][k/2][n] = bf16x2(W[2p], W[2p+1])
__global__ void pack_weights_kernel(const float* __restrict__ W, unsigned* __restrict__ out,
                                    int C, int N, int total)
{
    int i = blockIdx.x * blockDim.x + threadIdx.x;
    int stride = gridDim.x * blockDim.x;
    int halfC = C >> 1;
    for (int idx = i; idx < total; idx += stride) {
        int n = idx % N;
        int pg = idx / N;
        int tap = pg / halfC;
        int p = pg - tap * halfC;
        float w0 = W[(long)(tap * C + 2 * p) * N + n];
        float w1 = W[(long)(tap * C + 2 * p + 1) * N + n];
        __nv_bfloat162 v = __floats2bfloat162_rn(w0, w1);
        out[idx] = *(unsigned*)&v;
    }
}

__device__ __forceinline__ void mma_bf16(float* d, const unsigned* a, const unsigned* b) {
    asm volatile(
        "mma.sync.aligned.m16n8k16.row.col.f32.bf16.bf16.f32 "
        "{%0,%1,%2,%3}, {%4,%5,%6,%7}, {%8,%9}, {%0,%1,%2,%3};\n"
        : "+f"(d[0]), "+f"(d[1]), "+f"(d[2]), "+f"(d[3])
        : "r"(a[0]), "r"(a[1]), "r"(a[2]), "r"(a[3]), "r"(b[0]), "r"(b[1]));
}

__device__ __forceinline__ void cp16(unsigned int dst, const void* src, int sz) {
    asm volatile("cp.async.cg.shared.global [%0], [%1], 16, %2;"
                 :: "r"(dst), "l"(src), "r"(sz));
}

// ---------------------------------------------------------------------------
// Fused conv-gates GEMM, bf16 tensor core, 4-buffer pipeline.
// BM=128, BN=128, BK=32 (bf16 k), 256 threads = 8 warps (2M x 4N),
// warp tile 64x32 via m16n8k16 (4 m-frags x 4 n-frags, 2 k16 steps/tile).
// A: [128 rows][40 bf16] (80B rows, conflict-free). B: k-pairs [16][136 u32].
// ---------------------------------------------------------------------------
#define BM 128
#define BN 128
#define BK 32
#define LDA_U 20                          // u32 per A row (40 bf16)
#define LDB_U 136                         // u32 per B pair-row
#define A_BYTES (BM*LDA_U*4)              // 10240
#define B_BYTES (16*LDB_U*4)              // 8704
#define STAGE_BYTES (A_BYTES + B_BYTES)   // 18944
#define NBUF 4
#define CONV_SMEM_BYTES (NBUF*STAGE_BYTES)

__global__ __launch_bounds__(256)
void conv_gates_kernel(
    const __nv_bfloat16* __restrict__ srcA, int CA, int HA, int WA, long sAb, int padA,
    const unsigned* __restrict__ WpA, int kt0,
    const __nv_bfloat16* __restrict__ srcB, int CB, long sBb,
    const unsigned* __restrict__ WpB, int kt1,
    const float* __restrict__ xsrc, int xW, long xsb,
    const float* __restrict__ Wx, int useX,
    const float* __restrict__ bias,
    float* __restrict__ out, int OH, int OW, int N, int M)
{
    extern __shared__ char smem[];
    unsigned int smem_u = (unsigned int)__cvta_generic_to_shared(smem);

    const int tid = threadIdx.x;
    const int m0 = blockIdx.x * BM;
    const int n0 = blockIdx.y * BN;

    const int wid = tid >> 5, lane = tid & 31;
    const int wm = (wid >> 2) * 64;       // 2 warp rows
    const int wn = (wid & 3) * 32;        // 4 warp cols
    const int g = lane >> 2, tg = lane & 3;

    // staging coords
    const int am = tid >> 1;              // A row 0..127
    const int ach = (tid & 1);            // A 32B chunk 0/1
    const int bkp = tid >> 4;             // B pair-row 0..15
    const int bch = tid & 15;             // B 32B chunk 0..15

    int s_pb = 0, s_py = 0, s_px = 0;
    bool s_valid;
    {
        int gm = m0 + am;
        s_valid = gm < M;
        int r = s_valid ? gm : 0;
        s_px = r % OW; r /= OW;
        s_py = r % OH; s_pb = r / OH;
    }

    const int nt0 = 9 * kt0;
    const int ntiles = nt0 + 9 * kt1;

    float acc[4][4][4];
#pragma unroll
    for (int mi = 0; mi < 4; ++mi)
#pragma unroll
        for (int ni = 0; ni < 4; ++ni)
#pragma unroll
            for (int r = 0; r < 4; ++r) acc[mi][ni][r] = 0.f;

    auto stage = [&](int t, int buf) {
        int tap, K0, C, H, W, pad;
        long sb;
        const __nv_bfloat16* src;
        const unsigned* Wp;
        if (t < nt0) {
            tap = t / kt0; K0 = (t - tap * kt0) * BK;
            src = srcA; Wp = WpA; C = CA; H = HA; W = WA; sb = sAb; pad = padA;
        } else {
            int u = t - nt0;
            tap = u / kt1; K0 = (u - tap * kt1) * BK;
            src = srcB; Wp = WpB; C = CB; H = OH; W = OW; sb = sBb; pad = 1;
        }
        int y = s_py + tap / 3 - pad;
        int x = s_px + tap % 3 - pad;
        bool ok = s_valid && ((unsigned)y < (unsigned)H) && ((unsigned)x < (unsigned)W);
        const __nv_bfloat16* sp = ok
            ? src + (long)s_pb * sb + ((long)y * W + x) * C + K0 + ach * 16
            : src;
        int sz = ok ? 16 : 0;
        unsigned int da = smem_u + (unsigned)(buf * STAGE_BYTES + am * (LDA_U * 4) + ach * 32);
        cp16(da, sp, sz);
        cp16(da + 16, sp + 8, sz);
        const unsigned* wp = Wp + (long)(tap * (C >> 1) + (K0 >> 1) + bkp) * N + n0 + bch * 8;
        unsigned int db = smem_u + (unsigned)(buf * STAGE_BYTES + A_BYTES + bkp * (LDB_U * 4) + bch * 32);
        cp16(db, wp, 16);
        cp16(db + 16, wp + 4, 16);
    };

    auto compute = [&](int buf) {
        const unsigned* Au = (const unsigned*)(smem + buf * STAGE_BYTES);
        const unsigned* Bu = (const unsigned*)(smem + buf * STAGE_BYTES + A_BYTES);
#pragma unroll
        for (int ks = 0; ks < 2; ++ks) {
            unsigned a[4][4];
#pragma unroll
            for (int mi = 0; mi < 4; ++mi) {
                const unsigned* ap = Au + (wm + mi * 16 + g) * LDA_U + ks * 8 + tg;
                a[mi][0] = ap[0];
                a[mi][1] = ap[8 * LDA_U];
                a[mi][2] = ap[4];
                a[mi][3] = ap[8 * LDA_U + 4];
            }
            unsigned b[4][2];
#pragma unroll
            for (int ni = 0; ni < 4; ++ni) {
                const unsigned* bp = Bu + (ks * 8 + tg) * LDB_U + wn + ni * 8 + g;
                b[ni][0] = bp[0];
                b[ni][1] = bp[4 * LDB_U];
            }
#pragma unroll
            for (int mi = 0; mi < 4; ++mi)
#pragma unroll
                for (int ni = 0; ni < 4; ++ni)
                    mma_bf16(acc[mi][ni], a[mi], b[ni]);
        }
    };

    // ---- 4-buffer pipelined main loop (one sync per tile) ----
    stage(0, 0);
    asm volatile("cp.async.commit_group;");
    stage(1, 1);
    asm volatile("cp.async.commit_group;");
    for (int t = 0; t < ntiles; ++t) {
        if (t + 2 < ntiles) {
            stage(t + 2, (t + 2) & 3);
            asm volatile("cp.async.commit_group;");
            asm volatile("cp.async.wait_group 2;");
        } else if (t + 1 < ntiles) {
            asm volatile("cp.async.wait_group 1;");
        } else {
            asm volatile("cp.async.wait_group 0;");
        }
        __syncthreads();
        compute(t & 3);
    }

    // ---- fp32 epilogue for the C=1 input conv (layer 1 only) ----
    if (useX) {
        int epb[8], epy[8], epx[8];
        bool ev[8];
#pragma unroll
        for (int e = 0; e < 8; ++e) {
            int rr = m0 + wm + (e >> 1) * 16 + g + (e & 1) * 8;
            ev[e] = rr < M;
            int r2 = ev[e] ? rr : 0;
            epx[e] = r2 % OW; r2 /= OW;
            epy[e] = r2 % OH; epb[e] = r2 / OH;
        }
        for (int tap = 0; tap < 9; ++tap) {
            int dy = tap / 3, dx = tap % 3;   // VALID: pad 0
            float wv[4][2];
#pragma unroll
            for (int ni = 0; ni < 4; ++ni) {
                int col = n0 + wn + ni * 8 + 2 * tg;
                wv[ni][0] = Wx[tap * N + col];
                wv[ni][1] = Wx[tap * N + col + 1];
            }
#pragma unroll
            for (int e = 0; e < 8; ++e) if (ev[e]) {
                float xv = xsrc[(long)epb[e] * xsb + (long)(epy[e] + dy) * xW + (epx[e] + dx)];
#pragma unroll
                for (int ni = 0; ni < 4; ++ni) {
                    acc[e >> 1][ni][(e & 1) * 2 + 0] = fmaf(xv, wv[ni][0], acc[e >> 1][ni][(e & 1) * 2 + 0]);
                    acc[e >> 1][ni][(e & 1) * 2 + 1] = fmaf(xv, wv[ni][1], acc[e >> 1][ni][(e & 1) * 2 + 1]);
                }
            }
        }
    }

    // ---- writeback (+bias) ----
#pragma unroll
    for (int mi = 0; mi < 4; ++mi) {
#pragma unroll
        for (int ni = 0; ni < 4; ++ni) {
            int col = n0 + wn + ni * 8 + 2 * tg;
            float b0 = bias[col], b1 = bias[col + 1];
            int r0 = m0 + wm + mi * 16 + g;
            int r1 = r0 + 8;
            if (r0 < M) {
                float2 v; v.x = acc[mi][ni][0] + b0; v.y = acc[mi][ni][1] + b1;
                *(float2*)(out + (long)r0 * N + col) = v;
            }
            if (r1 < M) {
                float2 v; v.x = acc[mi][ni][2] + b0; v.y = acc[mi][ni][3] + b1;
                *(float2*)(out + (long)r1 * N + col) = v;
            }
        }
    }
}

// ---------------------------------------------------------------------------
// LSTM pointwise update. h written as bf16 (GEMM operand); optional fp32 copy.
// ---------------------------------------------------------------------------
__device__ __forceinline__ float sigmoidf_(float x) {
    return 1.f / (1.f + expf(-x));
}

__global__ void lstm_update_kernel(const float* __restrict__ gates,
                                   __nv_bfloat16* __restrict__ hb,
                                   float* __restrict__ hf,
                                   float* __restrict__ c,
                                   int M, int F)
{
    int idx = blockIdx.x * blockDim.x + threadIdx.x;
    int total = M * F / 4;
    if (idx >= total) return;
    int m = idx / (F / 4);
    int f4 = (idx % (F / 4)) * 4;
    const float* gp = gates + (long)m * 4 * F;
    float4 gi = *(const float4*)(gp + f4);
    float4 gf = *(const float4*)(gp + F + f4);
    float4 gg = *(const float4*)(gp + 2 * F + f4);
    float4 go = *(const float4*)(gp + 3 * F + f4);
    float4 cv = *(const float4*)(c + (long)m * F + f4);
    float4 cn, hn;
    cn.x = sigmoidf_(gf.x) * cv.x + sigmoidf_(gi.x) * tanhf(gg.x);
    cn.y = sigmoidf_(gf.y) * cv.y + sigmoidf_(gi.y) * tanhf(gg.y);
    cn.z = sigmoidf_(gf.z) * cv.z + sigmoidf_(gi.z) * tanhf(gg.z);
    cn.w = sigmoidf_(gf.w) * cv.w + sigmoidf_(gi.w) * tanhf(gg.w);
    hn.x = sigmoidf_(go.x) * tanhf(cn.x);
    hn.y = sigmoidf_(go.y) * tanhf(cn.y);
    hn.z = sigmoidf_(go.z) * tanhf(cn.z);
    hn.w = sigmoidf_(go.w) * tanhf(cn.w);
    *(float4*)(c + (long)m * F + f4) = cn;
    __nv_bfloat162 h01 = __floats2bfloat162_rn(hn.x, hn.y);
    __nv_bfloat162 h23 = __floats2bfloat162_rn(hn.z, hn.w);
    uint2 hp; hp.x = *(unsigned*)&h01; hp.y = *(unsigned*)&h23;
    *(uint2*)(hb + (long)m * F + f4) = hp;
    if (hf) *(float4*)(hf + (long)m * F + f4) = hn;
}

// ---------------------------------------------------------------------------
__global__ void dense_relu_kernel(const float* __restrict__ in,
                                  const float* __restrict__ W,
                                  const float* __restrict__ bias,
                                  float* __restrict__ out,
                                  int M, int K, int N, int do_relu)
{
    int idx = blockIdx.x * blockDim.x + threadIdx.x;
    if (idx >= M * N) return;
    int m = idx / N, n = idx % N;
    const float* ip = in + (long)m * K;
    float s = bias[n];
    for (int k = 0; k < K; ++k) s = fmaf(ip[k], W[k * N + n], s);
    if (do_relu) s = fmaxf(s, 0.f);
    out[idx] = s;
}

// ---------------------------------------------------------------------------
__global__ void final_fc_kernel(const float* __restrict__ dh,
                                const float* __restrict__ tin,
                                const float* __restrict__ locin,
                                const float* __restrict__ Wf1,
                                const float* __restrict__ bf1,
                                const float* __restrict__ Wf2,
                                const float* __restrict__ bf2,
                                float* __restrict__ out)
{
    int blk = blockIdx.x;              // = (b*30 + r)*28 + w
    int w = blk % 28;
    int r = (blk / 28) % 30;
    int b = blk / (28 * 30);

    __shared__ float v[64];
    __shared__ float red[64];
    int j = threadIdx.x;

    const float* src;
    if (r < 28)       src = dh    + (((long)(b * 28 + r)) * 28 + w) * 64;
    else if (r == 28) src = tin   + ((long)b * 28 + w) * 64;
    else              src = locin + ((long)b * 28 + w) * 64;
    v[j] = src[j];
    __syncthreads();

    float s = bf1[j];
#pragma unroll
    for (int k = 0; k < 64; ++k) s = fmaf(v[k], Wf1[k * 64 + j], s);
    s = fmaxf(s, 0.f) * Wf2[j];
    red[j] = s;
    __syncthreads();
    for (int off = 32; off > 0; off >>= 1) {
        if (j < off) red[j] += red[j + off];
        __syncthreads();
    }
    if (j == 0) out[blk] = red[0] + bf2[0];
}

// ---------------------------------------------------------------------------
extern "C" void kernel_launch(void* const* d_in, const int* in_sizes, int n_in,
                              void* d_out, int out_size)
{
    const float* x   = (const float*)d_in[0];
    const float* tt  = (const float*)d_in[1];
    const float* loc = (const float*)d_in[2];
    const float* Wx1 = (const float*)d_in[3];
    const float* Wh1 = (const float*)d_in[4];
    const float* b1  = (const float*)d_in[5];
    const float* Wx2 = (const float*)d_in[6];
    const float* Wh2 = (const float*)d_in[7];
    const float* b2  = (const float*)d_in[8];
    const float* Wd1 = (const float*)d_in[9];
    const float* bd1 = (const float*)d_in[10];
    const float* Wd2 = (const float*)d_in[11];
    const float* bd2 = (const float*)d_in[12];
    const float* Wf1 = (const float*)d_in[13];
    const float* bf1 = (const float*)d_in[14];
    const float* Wf2 = (const float*)d_in[15];
    const float* bf2 = (const float*)d_in[16];
    float* out = (float*)d_out;

    __nv_bfloat16 *h1b, *h2b;
    float *c1, *c2, *h2f, *gates1, *gates2, *dh;
    unsigned *Wh1p, *Wx2p, *Wh2p;
    cudaGetSymbolAddress((void**)&h1b, g_h1b);
    cudaGetSymbolAddress((void**)&c1, g_c1);
    cudaGetSymbolAddress((void**)&h2b, g_h2b);
    cudaGetSymbolAddress((void**)&c2, g_c2);
    cudaGetSymbolAddress((void**)&h2f, g_h2f);
    cudaGetSymbolAddress((void**)&gates1, g_gates1);
    cudaGetSymbolAddress((void**)&gates2, g_gates2);
    cudaGetSymbolAddress((void**)&dh, g_dh);
    cudaGetSymbolAddress((void**)&Wh1p, g_Wh1p);
    cudaGetSymbolAddress((void**)&Wx2p, g_Wx2p);
    cudaGetSymbolAddress((void**)&Wh2p, g_Wh2p);

    cudaFuncSetAttribute(conv_gates_kernel,
                         cudaFuncAttributeMaxDynamicSharedMemorySize, CONV_SMEM_BYTES);

    zero_state_kernel<<<1024, 256>>>();
    pack_weights_kernel<<<512, 256>>>(Wh1, Wh1p, 256, 1024, 9 * 128 * 1024);
    pack_weights_kernel<<<512, 256>>>(Wx2, Wx2p, 256, 512, 9 * 128 * 512);
    pack_weights_kernel<<<512, 256>>>(Wh2, Wh2p, 128, 512, 9 * 64 * 512);

    const int M1 = 8 * 30 * 30;   // 7200
    const int M2 = 8 * 28 * 28;   // 6272

    for (int ts = 0; ts < 10; ++ts) {
        // L1: recurrent conv GEMM (h1b, SAME, C=256) + x-conv fp32 epilogue
        conv_gates_kernel<<<dim3((M1 + BM - 1) / BM, 1024 / BN), 256, CONV_SMEM_BYTES>>>(
            h1b, 256, 30, 30, (long)30 * 30 * 256, 1, Wh1p, /*kt0=*/0,
            h1b, 256, (long)30 * 30 * 256, Wh1p, /*kt1=*/8,
            x + (long)ts * 32 * 32, 32, (long)10 * 32 * 32, Wx1, /*useX=*/1,
            b1, gates1, 30, 30, 1024, M1);
        lstm_update_kernel<<<(M1 * 256 / 4 + 255) / 256, 256>>>(gates1, h1b, nullptr, c1, M1, 256);

        // L2: input conv (h1b, VALID, C=256) + recurrent conv (h2b, SAME, C=128)
        conv_gates_kernel<<<dim3((M2 + BM - 1) / BM, 512 / BN), 256, CONV_SMEM_BYTES>>>(
            h1b, 256, 30, 30, (long)30 * 30 * 256, 0, Wx2p, /*kt0=*/8,
            h2b, 128, (long)28 * 28 * 128, Wh2p, /*kt1=*/4,
            x, 32, (long)10 * 32 * 32, Wx1, /*useX=*/0,
            b2, gates2, 28, 28, 512, M2);
        lstm_update_kernel<<<(M2 * 128 / 4 + 255) / 256, 256>>>(gates2, h2b, h2f, c2, M2, 128);
    }

    dense_relu_kernel<<<(M2 * 256 + 255) / 256, 256>>>(h2f, Wd1, bd1, gates2, M2, 128, 256, 1);
    dense_relu_kernel<<<(M2 * 64 + 255) / 256, 256>>>(gates2, Wd2, bd2, dh, M2, 256, 64, 1);

    final_fc_kernel<<<8 * 30 * 28, 64>>>(dh, tt, loc, Wf1, bf1, Wf2, bf2, out);
}

// round 7
// speedup vs baseline: 4.7847x; 1.0799x over previous
#include <cuda_runtime.h>
#include <cuda_bf16.h>
#include <cstdint>
#include <math.h>

// ---------------------------------------------------------------------------
// Q6Model: 2-layer ConvLSTM (T=10) + dense head + concat + FC head
// Round 7 = Round 6 + ping-pong h buffers (fixes cross-block RAW race on h).
// Gate-interleaved weights (n' = 4f+g), LSTM update fused into conv epilogue,
// bf16 m16n8k16 GEMM core, 4-buffer cp.async ring. 28 launches.
// ---------------------------------------------------------------------------

#define H1N (8*30*30*256)
#define H2N (8*28*28*128)

__device__ __nv_bfloat16 g_h1b[2][H1N];   // ping-pong
__device__ float         g_c1[H1N];
__device__ __nv_bfloat16 g_h2b[2][H2N];   // ping-pong
__device__ float         g_c2[H2N];
__device__ float         g_h2f[H2N];      // fp32 copy of h2 for dense head
__device__ float g_scr256[8*28*28*256];   // dense head scratch
__device__ float g_dh[8*28*28*64];
// packed bf16x2 weights, gate-interleaved cols: [tap][k/2][n'], n' = 4f+g
__device__ unsigned g_Wh1p[9*128*1024];
__device__ unsigned g_Wx2p[9*128*512];
__device__ unsigned g_Wh2p[9*64*512];
// gate-interleaved fp32 x-conv weights for L1 epilogue
__device__ float g_Wx1i[9*1024];

__global__ void zero_state_kernel() {
    int i = blockIdx.x * blockDim.x + threadIdx.x;
    int stride = gridDim.x * blockDim.x;
    unsigned* h1u = (unsigned*)g_h1b;
    unsigned* h2u = (unsigned*)g_h2b;
    for (int k = i; k < H1N; k += stride) g_c1[k] = 0.f;
    for (int k = i; k < H1N; k += stride) h1u[k] = 0u;   // both buffers (2*H1N bf16 = H1N u32... covers both halves? no)
    for (int k = i; k < H2N; k += stride) g_c2[k] = 0.f;
    for (int k = i; k < H2N; k += stride) h2u[k] = 0u;
}
// note: 2 buffers * H1N bf16 = H1N u32 total -> the loops above zero exactly
// both ping-pong buffers for each layer.

// W[tap][k][n] fp32 -> out[tap][k/2][n'] bf16x2, n' = 4*(n%F) + n/F
__global__ void pack_weights_kernel(const float* __restrict__ W, unsigned* __restrict__ out,
                                    int C, int N, int total)
{
    int i = blockIdx.x * blockDim.x + threadIdx.x;
    int stride = gridDim.x * blockDim.x;
    int halfC = C >> 1;
    int F = N >> 2;
    for (int idx = i; idx < total; idx += stride) {
        int n = idx % N;
        int pg = idx / N;
        int tap = pg / halfC;
        int p = pg - tap * halfC;
        int np = 4 * (n % F) + (n / F);
        float w0 = W[(long)(tap * C + 2 * p) * N + n];
        float w1 = W[(long)(tap * C + 2 * p + 1) * N + n];
        __nv_bfloat162 v = __floats2bfloat162_rn(w0, w1);
        out[(long)pg * N + np] = *(unsigned*)&v;
    }
}

// Wx[tap][n] fp32 -> out[tap][n'] fp32 (gate interleave)
__global__ void interleave_wx_kernel(const float* __restrict__ W, float* __restrict__ out,
                                     int N, int total)
{
    int i = blockIdx.x * blockDim.x + threadIdx.x;
    int stride = gridDim.x * blockDim.x;
    int F = N >> 2;
    for (int idx = i; idx < total; idx += stride) {
        int n = idx % N;
        int tap = idx / N;
        int np = 4 * (n % F) + (n / F);
        out[tap * N + np] = W[idx];
    }
}

__device__ __forceinline__ void mma_bf16(float* d, const unsigned* a, const unsigned* b) {
    asm volatile(
        "mma.sync.aligned.m16n8k16.row.col.f32.bf16.bf16.f32 "
        "{%0,%1,%2,%3}, {%4,%5,%6,%7}, {%8,%9}, {%0,%1,%2,%3};\n"
        : "+f"(d[0]), "+f"(d[1]), "+f"(d[2]), "+f"(d[3])
        : "r"(a[0]), "r"(a[1]), "r"(a[2]), "r"(a[3]), "r"(b[0]), "r"(b[1]));
}

__device__ __forceinline__ void cp16(unsigned int dst, const void* src, int sz) {
    asm volatile("cp.async.cg.shared.global [%0], [%1], 16, %2;"
                 :: "r"(dst), "l"(src), "r"(sz));
}

__device__ __forceinline__ float sigmoidf_(float x) {
    return 1.f / (1.f + expf(-x));
}

// ---------------------------------------------------------------------------
// Fused conv-gates GEMM + LSTM update, bf16 tensor core, 4-buffer pipeline.
// BM=128, BN=128, BK=32, 256 threads = 8 warps (2M x 4N), warp tile 64x32.
// Columns are gate-interleaved: block covers 32 features x 4 gates.
// Epilogue: acc -> smem S[4][128][33] (gate-major) -> sigmoid/tanh -> h, c.
// Reads h from prev buffer, writes next buffer (no cross-block hazard).
// ---------------------------------------------------------------------------
#define BM 128
#define BN 128
#define BK 32
#define LDA_U 20                          // u32 per A row (40 bf16)
#define LDB_U 136                         // u32 per B pair-row
#define A_BYTES (BM*LDA_U*4)              // 10240
#define B_BYTES (16*LDB_U*4)              // 8704
#define STAGE_BYTES (A_BYTES + B_BYTES)   // 18944
#define NBUF 4
#define CONV_SMEM_BYTES (NBUF*STAGE_BYTES)
#define SROW 33
#define SGATE (128*SROW)                  // 4224 words per gate plane

__global__ __launch_bounds__(256)
void conv_lstm_kernel(
    const __nv_bfloat16* __restrict__ srcA, int CA, int HA, int WA, long sAb, int padA,
    const unsigned* __restrict__ WpA, int kt0,
    const __nv_bfloat16* __restrict__ srcB, int CB, long sBb,
    const unsigned* __restrict__ WpB, int kt1,
    const float* __restrict__ xsrc, int xW, long xsb,
    const float* __restrict__ WxI, int useX,
    const float* __restrict__ bias,
    __nv_bfloat16* __restrict__ hb, float* __restrict__ hf,
    float* __restrict__ c,
    int OH, int OW, int N, int M)
{
    extern __shared__ char smem[];
    unsigned int smem_u = (unsigned int)__cvta_generic_to_shared(smem);

    const int tid = threadIdx.x;
    const int m0 = blockIdx.x * BM;
    const int n0 = blockIdx.y * BN;

    const int wid = tid >> 5, lane = tid & 31;
    const int wm = (wid >> 2) * 64;       // 2 warp rows
    const int wn = (wid & 3) * 32;        // 4 warp cols
    const int g = lane >> 2, tg = lane & 3;

    // staging coords
    const int am = tid >> 1;              // A row 0..127
    const int ach = (tid & 1);            // A 32B chunk 0/1
    const int bkp = tid >> 4;             // B pair-row 0..15
    const int bch = tid & 15;             // B 32B chunk 0..15

    int s_pb = 0, s_py = 0, s_px = 0;
    bool s_valid;
    {
        int gm = m0 + am;
        s_valid = gm < M;
        int r = s_valid ? gm : 0;
        s_px = r % OW; r /= OW;
        s_py = r % OH; s_pb = r / OH;
    }

    const int nt0 = 9 * kt0;
    const int ntiles = nt0 + 9 * kt1;

    float acc[4][4][4];
#pragma unroll
    for (int mi = 0; mi < 4; ++mi)
#pragma unroll
        for (int ni = 0; ni < 4; ++ni)
#pragma unroll
            for (int r = 0; r < 4; ++r) acc[mi][ni][r] = 0.f;

    auto stage = [&](int t, int buf) {
        int tap, K0, C, H, W, pad;
        long sb;
        const __nv_bfloat16* src;
        const unsigned* Wp;
        if (t < nt0) {
            tap = t / kt0; K0 = (t - tap * kt0) * BK;
            src = srcA; Wp = WpA; C = CA; H = HA; W = WA; sb = sAb; pad = padA;
        } else {
            int u = t - nt0;
            tap = u / kt1; K0 = (u - tap * kt1) * BK;
            src = srcB; Wp = WpB; C = CB; H = OH; W = OW; sb = sBb; pad = 1;
        }
        int y = s_py + tap / 3 - pad;
        int x = s_px + tap % 3 - pad;
        bool ok = s_valid && ((unsigned)y < (unsigned)H) && ((unsigned)x < (unsigned)W);
        const __nv_bfloat16* sp = ok
            ? src + (long)s_pb * sb + ((long)y * W + x) * C + K0 + ach * 16
            : src;
        int sz = ok ? 16 : 0;
        unsigned int da = smem_u + (unsigned)(buf * STAGE_BYTES + am * (LDA_U * 4) + ach * 32);
        cp16(da, sp, sz);
        cp16(da + 16, sp + 8, sz);
        const unsigned* wp = Wp + (long)(tap * (C >> 1) + (K0 >> 1) + bkp) * N + n0 + bch * 8;
        unsigned int db = smem_u + (unsigned)(buf * STAGE_BYTES + A_BYTES + bkp * (LDB_U * 4) + bch * 32);
        cp16(db, wp, 16);
        cp16(db + 16, wp + 4, 16);
    };

    auto compute = [&](int buf) {
        const unsigned* Au = (const unsigned*)(smem + buf * STAGE_BYTES);
        const unsigned* Bu = (const unsigned*)(smem + buf * STAGE_BYTES + A_BYTES);
#pragma unroll
        for (int ks = 0; ks < 2; ++ks) {
            unsigned a[4][4];
#pragma unroll
            for (int mi = 0; mi < 4; ++mi) {
                const unsigned* ap = Au + (wm + mi * 16 + g) * LDA_U + ks * 8 + tg;
                a[mi][0] = ap[0];
                a[mi][1] = ap[8 * LDA_U];
                a[mi][2] = ap[4];
                a[mi][3] = ap[8 * LDA_U + 4];
            }
            unsigned b[4][2];
#pragma unroll
            for (int ni = 0; ni < 4; ++ni) {
                const unsigned* bp = Bu + (ks * 8 + tg) * LDB_U + wn + ni * 8 + g;
                b[ni][0] = bp[0];
                b[ni][1] = bp[4 * LDB_U];
            }
#pragma unroll
            for (int mi = 0; mi < 4; ++mi)
#pragma unroll
                for (int ni = 0; ni < 4; ++ni)
                    mma_bf16(acc[mi][ni], a[mi], b[ni]);
        }
    };

    // ---- 4-buffer pipelined main loop (one sync per tile) ----
    stage(0, 0);
    asm volatile("cp.async.commit_group;");
    stage(1, 1);
    asm volatile("cp.async.commit_group;");
    for (int t = 0; t < ntiles; ++t) {
        if (t + 2 < ntiles) {
            stage(t + 2, (t + 2) & 3);
            asm volatile("cp.async.commit_group;");
            asm volatile("cp.async.wait_group 2;");
        } else if (t + 1 < ntiles) {
            asm volatile("cp.async.wait_group 1;");
        } else {
            asm volatile("cp.async.wait_group 0;");
        }
        __syncthreads();
        compute(t & 3);
    }

    // ---- fp32 epilogue for the C=1 input conv (layer 1 only), interleaved W
    if (useX) {
        int epb[8], epy[8], epx[8];
        bool ev[8];
#pragma unroll
        for (int e = 0; e < 8; ++e) {
            int rr = m0 + wm + (e >> 1) * 16 + g + (e & 1) * 8;
            ev[e] = rr < M;
            int r2 = ev[e] ? rr : 0;
            epx[e] = r2 % OW; r2 /= OW;
            epy[e] = r2 % OH; epb[e] = r2 / OH;
        }
        for (int tap = 0; tap < 9; ++tap) {
            int dy = tap / 3, dx = tap % 3;   // VALID: pad 0
            float wv[4][2];
#pragma unroll
            for (int ni = 0; ni < 4; ++ni) {
                int col = n0 + wn + ni * 8 + 2 * tg;
                wv[ni][0] = WxI[tap * N + col];
                wv[ni][1] = WxI[tap * N + col + 1];
            }
#pragma unroll
            for (int e = 0; e < 8; ++e) if (ev[e]) {
                float xv = xsrc[(long)epb[e] * xsb + (long)(epy[e] + dy) * xW + (epx[e] + dx)];
#pragma unroll
                for (int ni = 0; ni < 4; ++ni) {
                    acc[e >> 1][ni][(e & 1) * 2 + 0] = fmaf(xv, wv[ni][0], acc[e >> 1][ni][(e & 1) * 2 + 0]);
                    acc[e >> 1][ni][(e & 1) * 2 + 1] = fmaf(xv, wv[ni][1], acc[e >> 1][ni][(e & 1) * 2 + 1]);
                }
            }
        }
    }

    // ---- fused LSTM epilogue ----
    // Spill acc to S[gate][row][feat] (gate-major, padded), then pointwise.
    __syncthreads();                       // all MMA reads of ring buffers done
    float* S = (float*)smem;
#pragma unroll
    for (int mi = 0; mi < 4; ++mi) {
#pragma unroll
        for (int ni = 0; ni < 4; ++ni) {
            int c0 = wn + ni * 8 + 2 * tg;     // local interleaved col (even)
            int c1 = c0 + 1;
            int r0 = wm + mi * 16 + g;
            int r1 = r0 + 8;
            S[(c0 & 3) * SGATE + r0 * SROW + (c0 >> 2)] = acc[mi][ni][0];
            S[(c1 & 3) * SGATE + r0 * SROW + (c1 >> 2)] = acc[mi][ni][1];
            S[(c0 & 3) * SGATE + r1 * SROW + (c0 >> 2)] = acc[mi][ni][2];
            S[(c1 & 3) * SGATE + r1 * SROW + (c1 >> 2)] = acc[mi][ni][3];
        }
    }
    __syncthreads();

    {
        const int F = N >> 2;
        const int f0 = blockIdx.y * 32;
        const int fl = tid & 31;           // feature lane -> coalesced h/c
        const int rbase = (tid >> 5) * 16; // 8 warps x 16 rows
        const int fg = f0 + fl;
        const float bi = bias[fg];
        const float bfr = bias[F + fg];
        const float bc = bias[2 * F + fg];
        const float bo = bias[3 * F + fg];
#pragma unroll 4
        for (int rr = 0; rr < 16; ++rr) {
            int r = rbase + rr;
            int gm = m0 + r;
            if (gm < M) {
                float zi = S[0 * SGATE + r * SROW + fl] + bi;
                float zf = S[1 * SGATE + r * SROW + fl] + bfr;
                float zc = S[2 * SGATE + r * SROW + fl] + bc;
                float zo = S[3 * SGATE + r * SROW + fl] + bo;
                long ci = (long)gm * F + fg;
                float cn = sigmoidf_(zf) * c[ci] + sigmoidf_(zi) * tanhf(zc);
                float hn = sigmoidf_(zo) * tanhf(cn);
                c[ci] = cn;
                hb[ci] = __float2bfloat16(hn);
                if (hf) hf[ci] = hn;
            }
        }
    }
}

// ---------------------------------------------------------------------------
__global__ void dense_relu_kernel(const float* __restrict__ in,
                                  const float* __restrict__ W,
                                  const float* __restrict__ bias,
                                  float* __restrict__ out,
                                  int M, int K, int N, int do_relu)
{
    int idx = blockIdx.x * blockDim.x + threadIdx.x;
    if (idx >= M * N) return;
    int m = idx / N, n = idx % N;
    const float* ip = in + (long)m * K;
    float s = bias[n];
    for (int k = 0; k < K; ++k) s = fmaf(ip[k], W[k * N + n], s);
    if (do_relu) s = fmaxf(s, 0.f);
    out[idx] = s;
}

// ---------------------------------------------------------------------------
__global__ void final_fc_kernel(const float* __restrict__ dh,
                                const float* __restrict__ tin,
                                const float* __restrict__ locin,
                                const float* __restrict__ Wf1,
                                const float* __restrict__ bf1,
                                const float* __restrict__ Wf2,
                                const float* __restrict__ bf2,
                                float* __restrict__ out)
{
    int blk = blockIdx.x;              // = (b*30 + r)*28 + w
    int w = blk % 28;
    int r = (blk / 28) % 30;
    int b = blk / (28 * 30);

    __shared__ float v[64];
    __shared__ float red[64];
    int j = threadIdx.x;

    const float* src;
    if (r < 28)       src = dh    + (((long)(b * 28 + r)) * 28 + w) * 64;
    else if (r == 28) src = tin   + ((long)b * 28 + w) * 64;
    else              src = locin + ((long)b * 28 + w) * 64;
    v[j] = src[j];
    __syncthreads();

    float s = bf1[j];
#pragma unroll
    for (int k = 0; k < 64; ++k) s = fmaf(v[k], Wf1[k * 64 + j], s);
    s = fmaxf(s, 0.f) * Wf2[j];
    red[j] = s;
    __syncthreads();
    for (int off = 32; off > 0; off >>= 1) {
        if (j < off) red[j] += red[j + off];
        __syncthreads();
    }
    if (j == 0) out[blk] = red[0] + bf2[0];
}

// ---------------------------------------------------------------------------
extern "C" void kernel_launch(void* const* d_in, const int* in_sizes, int n_in,
                              void* d_out, int out_size)
{
    const float* x   = (const float*)d_in[0];
    const float* tt  = (const float*)d_in[1];
    const float* loc = (const float*)d_in[2];
    const float* Wx1 = (const float*)d_in[3];
    const float* Wh1 = (const float*)d_in[4];
    const float* b1  = (const float*)d_in[5];
    const float* Wx2 = (const float*)d_in[6];
    const float* Wh2 = (const float*)d_in[7];
    const float* b2  = (const float*)d_in[8];
    const float* Wd1 = (const float*)d_in[9];
    const float* bd1 = (const float*)d_in[10];
    const float* Wd2 = (const float*)d_in[11];
    const float* bd2 = (const float*)d_in[12];
    const float* Wf1 = (const float*)d_in[13];
    const float* bf1 = (const float*)d_in[14];
    const float* Wf2 = (const float*)d_in[15];
    const float* bf2 = (const float*)d_in[16];
    float* out = (float*)d_out;

    __nv_bfloat16 *h1b0, *h1b1, *h2b0, *h2b1;
    float *c1, *c2, *h2f, *scr256, *dh, *Wx1i;
    unsigned *Wh1p, *Wx2p, *Wh2p;
    cudaGetSymbolAddress((void**)&h1b0, g_h1b);
    h1b1 = h1b0 + H1N;
    cudaGetSymbolAddress((void**)&h2b0, g_h2b);
    h2b1 = h2b0 + H2N;
    cudaGetSymbolAddress((void**)&c1, g_c1);
    cudaGetSymbolAddress((void**)&c2, g_c2);
    cudaGetSymbolAddress((void**)&h2f, g_h2f);
    cudaGetSymbolAddress((void**)&scr256, g_scr256);
    cudaGetSymbolAddress((void**)&dh, g_dh);
    cudaGetSymbolAddress((void**)&Wh1p, g_Wh1p);
    cudaGetSymbolAddress((void**)&Wx2p, g_Wx2p);
    cudaGetSymbolAddress((void**)&Wh2p, g_Wh2p);
    cudaGetSymbolAddress((void**)&Wx1i, g_Wx1i);

    cudaFuncSetAttribute(conv_lstm_kernel,
                         cudaFuncAttributeMaxDynamicSharedMemorySize, CONV_SMEM_BYTES);

    zero_state_kernel<<<1024, 256>>>();
    pack_weights_kernel<<<512, 256>>>(Wh1, Wh1p, 256, 1024, 9 * 128 * 1024);
    pack_weights_kernel<<<512, 256>>>(Wx2, Wx2p, 256, 512, 9 * 128 * 512);
    pack_weights_kernel<<<512, 256>>>(Wh2, Wh2p, 128, 512, 9 * 64 * 512);
    interleave_wx_kernel<<<36, 256>>>(Wx1, Wx1i, 1024, 9 * 1024);

    const int M1 = 8 * 30 * 30;   // 7200
    const int M2 = 8 * 28 * 28;   // 6272

    for (int ts = 0; ts < 10; ++ts) {
        int p = ts & 1;
        __nv_bfloat16* h1r = p ? h1b1 : h1b0;   // read h1(t-1)
        __nv_bfloat16* h1w = p ? h1b0 : h1b1;   // write h1(t)
        __nv_bfloat16* h2r = p ? h2b1 : h2b0;
        __nv_bfloat16* h2w = p ? h2b0 : h2b1;

        // L1: recurrent conv GEMM (h1r, SAME, C=256) + x-conv epilogue + LSTM -> h1w
        conv_lstm_kernel<<<dim3((M1 + BM - 1) / BM, 1024 / BN), 256, CONV_SMEM_BYTES>>>(
            h1r, 256, 30, 30, (long)30 * 30 * 256, 1, Wh1p, /*kt0=*/0,
            h1r, 256, (long)30 * 30 * 256, Wh1p, /*kt1=*/8,
            x + (long)ts * 32 * 32, 32, (long)10 * 32 * 32, Wx1i, /*useX=*/1,
            b1, h1w, nullptr, c1, 30, 30, 1024, M1);

        // L2: input conv (h1w = h1(t), VALID, C=256) + recurrent conv (h2r, SAME) + LSTM -> h2w
        conv_lstm_kernel<<<dim3((M2 + BM - 1) / BM, 512 / BN), 256, CONV_SMEM_BYTES>>>(
            h1w, 256, 30, 30, (long)30 * 30 * 256, 0, Wx2p, /*kt0=*/8,
            h2r, 128, (long)28 * 28 * 128, Wh2p, /*kt1=*/4,
            x, 32, (long)10 * 32 * 32, Wx1i, /*useX=*/0,
            b2, h2w, h2f, c2, 28, 28, 512, M2);
    }

    dense_relu_kernel<<<(M2 * 256 + 255) / 256, 256>>>(h2f, Wd1, bd1, scr256, M2, 128, 256, 1);
    dense_relu_kernel<<<(M2 * 64 + 255) / 256, 256>>>(scr256, Wd2, bd2, dh, M2, 256, 64, 1);

    final_fc_kernel<<<8 * 30 * 28, 64>>>(dh, tt, loc, Wf1, bf1, Wf2, bf2, out);
}